// round 8
// baseline (speedup 1.0000x reference)
#include <cuda_runtime.h>
#include <math.h>
#include <stdint.h>

#define B_BATCH 2
#define NPTS    20480
#define MPTS    2048
#define CDIM    256
#define ND      16384
#define NS      512
#define NVIEW   800
#define GTH     0.001f

#define TFPS    512
#define PMAX    22                /* points per thread, contiguous sorted  */
#define WPTS    (PMAX*32)         /* 704 points per warp                   */
#define NVMAX   (TFPS*PMAX)       /* 11264 compacted-point capacity        */

/* output offsets (floats), concatenated in reference return order */
#define O_XYZ   0
#define O_FEAT  (B_BATCH*MPTS*3)                    /* 12288    */
#define O_AFF   (O_FEAT + B_BATCH*MPTS*CDIM)        /* 1060864  */
#define O_VIEW  (O_AFF + B_BATCH*ND)                /* 1093632  */
#define O_GRASP (O_VIEW + B_BATCH*NS*NVIEW)         /* 1912832  */

/* fps smem layout (bytes) */
#define SM_PS    0                          /* float4 ps[NVMAX]   (180224) */
#define SM_PERM  (SM_PS + NVMAX*16)         /* int perm[NVMAX]    (45056)  */
#define SM_SCAN  (SM_PERM + NVMAX*4)        /* int scan[512] (hist too)    */
#define SM_BALL  (SM_SCAN + TFPS*4)         /* float4 ball[16]    (256)    */
#define SM_AUX   (SM_BALL + 16*16)          /* bbox[6] redW[16] bciA[2]    */
#define SM_TOTAL (SM_AUX + 24*4)

typedef unsigned long long ull;

__device__ float g_views[NVIEW*3];
__device__ int   g_oi[B_BATCH*NPTS];     /* compacted -> original index */
__device__ float g_cc[B_BATCH*NPTS*3];   /* fallback compacted coords   */
__device__ int   g_fps[B_BATCH*MPTS];    /* FPS-selected original idx   */
__device__ int   g_vind[B_BATCH*NS*3];   /* per-approach best view      */

/* ---------- packed f32x2 helpers (per-lane identical to scalar .rn) ---------- */
__device__ __forceinline__ ull pk2(float a, float b){
    ull r; asm("mov.b64 %0, {%1,%2};" : "=l"(r) : "f"(a), "f"(b)); return r;
}
__device__ __forceinline__ void upk2(ull v, float &a, float &b){
    asm("mov.b64 {%0,%1}, %2;" : "=f"(a), "=f"(b) : "l"(v));
}
__device__ __forceinline__ ull add2(ull a, ull b){
    ull r; asm("add.rn.f32x2 %0, %1, %2;" : "=l"(r) : "l"(a), "l"(b)); return r;
}
__device__ __forceinline__ ull mul2(ull a, ull b){
    ull r; asm("mul.rn.f32x2 %0, %1, %2;" : "=l"(r) : "l"(a), "l"(b)); return r;
}

/* orderable-uint encoding for float atomic min/max */
__device__ __forceinline__ unsigned fenc(float f){
    unsigned u = __float_as_uint(f);
    return (u & 0x80000000u) ? ~u : (u | 0x80000000u);
}
__device__ __forceinline__ float fdec(unsigned u){
    u = (u & 0x80000000u) ? (u & 0x7FFFFFFFu) : ~u;
    return __uint_as_float(u);
}
/* 3-bit-per-dim morton interleave */
__device__ __forceinline__ unsigned mor3(unsigned ix, unsigned iy, unsigned iz){
    unsigned c = 0;
    #pragma unroll
    for (int k = 0; k < 3; k++)
        c |= (((ix>>k)&1u)<<(3*k+2)) | (((iy>>k)&1u)<<(3*k+1)) | (((iz>>k)&1u)<<(3*k));
    return c;
}

/* ---------- view templates: fp64 Fibonacci sphere, matches numpy ---------- */
__global__ void views_kernel(){
    const double phi = (sqrt(5.0) - 1.0) * 0.5;
    for (int i = threadIdx.x; i < NVIEW; i += blockDim.x){
        double zi = (2.0 * (double)i + 1.0) / (double)NVIEW - 1.0;
        double r2 = 1.0 - zi * zi; if (r2 < 0.0) r2 = 0.0;
        double r  = sqrt(r2);
        double ang = 2.0 * 3.141592653589793 * (double)i * phi;
        g_views[i*3+0] = (float)(r * cos(ang));
        g_views[i*3+1] = (float)(r * sin(ang));
        g_views[i*3+2] = (float)zi;
    }
}

/* ---------- zero-fill the scatter outputs (128-bit stores) ---------- */
__global__ void zero_kernel(float4* __restrict__ p, size_t n4){
    size_t stride = (size_t)gridDim.x * blockDim.x;
    for (size_t i = (size_t)blockIdx.x * blockDim.x + threadIdx.x; i < n4; i += stride)
        p[i] = make_float4(0.f, 0.f, 0.f, 0.f);
}

/* ---------- generic block argmax (fallback path only) ---------- */
__device__ __forceinline__ int block_argmax(float bestd, int bestc,
                                            float* redD, int* redC, int* bci, int t){
    #pragma unroll
    for (int off = 16; off > 0; off >>= 1){
        float od = __shfl_down_sync(0xffffffffu, bestd, off);
        int   oc = __shfl_down_sync(0xffffffffu, bestc, off);
        if (od > bestd || (od == bestd && oc < bestc)){ bestd = od; bestc = oc; }
    }
    if ((t & 31) == 0){ redD[t>>5] = bestd; redC[t>>5] = bestc; }
    __syncthreads();
    if (t < 32){
        float bd  = (t < 16) ? redD[t] : -3.3e38f;
        int   bcv = (t < 16) ? redC[t] : 0x7fffffff;
        #pragma unroll
        for (int off = 8; off > 0; off >>= 1){
            float od = __shfl_down_sync(0xffffffffu, bd, off);
            int   oc = __shfl_down_sync(0xffffffffu, bcv, off);
            if (od > bd || (od == bd && oc < bcv)){ bd = od; bcv = oc; }
        }
        if (t == 0) *bci = bcv;
    }
    __syncthreads();
    return *bci;
}

/* ---------- masked FPS: one block per batch, warp-granular pruning ---------- */
__global__ void __launch_bounds__(TFPS, 1)
fps_kernel(const float* __restrict__ xyz, const float* __restrict__ gsc){
    extern __shared__ unsigned char fsm[];
    const int b = blockIdx.x;
    const int t = threadIdx.x;
    const int lane = t & 31;
    const int w = t >> 5;
    const float* X = xyz + (size_t)b * NPTS * 3;
    const float* G = gsc + (size_t)b * NPTS;

    float4*   ps   = (float4*)(fsm + SM_PS);
    int*      perm = (int*)(fsm + SM_PERM);
    int*      scan = (int*)(fsm + SM_SCAN);
    float4*   ball = (float4*)(fsm + SM_BALL);
    unsigned* aux  = (unsigned*)(fsm + SM_AUX);
    unsigned* bbox = aux;            /* [6]  */
    unsigned* redW = aux + 6;        /* [16] */
    int*      bciA = (int*)(aux + 22);/* [2]  */

    /* ---- order-preserving compaction of graspable points ---- */
    const int CH = NPTS / TFPS;  /* 40 */
    int base = t * CH;
    int cnt = 0;
    for (int j = 0; j < CH; j++) cnt += (G[base + j] > GTH) ? 1 : 0;
    scan[t] = cnt;
    __syncthreads();
    for (int off = 1; off < TFPS; off <<= 1){
        int v = scan[t];
        int a = (t >= off) ? scan[t - off] : 0;
        __syncthreads();
        scan[t] = v + a;
        __syncthreads();
    }
    int Nv  = scan[TFPS - 1];
    int pos = scan[t] - cnt;
    bool fast = (Nv <= NVMAX);
    for (int j = 0; j < CH; j++){
        int idx = base + j;
        if (G[idx] > GTH){
            float x = X[idx*3+0], y = X[idx*3+1], z = X[idx*3+2];
            if (fast){
                ps[pos] = make_float4(x, y, z, 0.f);
            } else {
                size_t gp = ((size_t)b * NPTS + pos) * 3;
                g_cc[gp] = x; g_cc[gp+1] = y; g_cc[gp+2] = z;
            }
            g_oi[b*NPTS + pos] = idx;
            pos++;
        }
    }
    __syncthreads();

    if (Nv <= 0){
        for (int m = t; m < MPTS; m += TFPS) g_fps[b*MPTS + m] = 0;
        return;
    }

    if (!fast){
        /* fallback (statistically unreachable): dists in smem, coords global */
        float* dst  = (float*)ps;
        float* redD = (float*)scan;
        int*   redC = (int*)(redD + 16);
        int*   bci  = redC + 16;
        for (int c = t; c < Nv; c += TFPS) dst[c] = 1e10f;
        if (t == 0) g_fps[b*MPTS] = g_oi[b*NPTS];
        __syncthreads();
        float px = g_cc[(size_t)b*NPTS*3+0];
        float py = g_cc[(size_t)b*NPTS*3+1];
        float pz = g_cc[(size_t)b*NPTS*3+2];
        for (int m = 1; m < MPTS; m++){
            float bestd = -1.0f; int bestc = 0x7fffffff;
            for (int c = t; c < Nv; c += TFPS){
                const float* P = &g_cc[((size_t)b*NPTS + c)*3];
                float dx = __fadd_rn(P[0], -px);
                float dy = __fadd_rn(P[1], -py);
                float dz = __fadd_rn(P[2], -pz);
                float d  = __fadd_rn(__fadd_rn(__fmul_rn(dx,dx), __fmul_rn(dy,dy)),
                                     __fmul_rn(dz,dz));
                float nd = fminf(dst[c], d);
                dst[c] = nd;
                if (nd > bestd){ bestd = nd; bestc = c; }
            }
            int wc = block_argmax(bestd, bestc, redD, redC, bci, t);
            if (t == 0) g_fps[b*MPTS + m] = g_oi[b*NPTS + wc];
            const float* P = &g_cc[((size_t)b*NPTS + wc)*3];
            px = P[0]; py = P[1]; pz = P[2];
            __syncthreads();
        }
        return;
    }

    /* ================= fast path ================= */

    /* ---- bounding box (orderable-uint atomics) ---- */
    if (t < 3) bbox[t] = 0xffffffffu;
    if (t >= 3 && t < 6) bbox[t] = 0u;
    __syncthreads();
    {
        float mnx=3e38f,mny=3e38f,mnz=3e38f, mxx=-3e38f,mxy=-3e38f,mxz=-3e38f;
        for (int c = t; c < Nv; c += TFPS){
            float4 P = ps[c];
            mnx=fminf(mnx,P.x); mny=fminf(mny,P.y); mnz=fminf(mnz,P.z);
            mxx=fmaxf(mxx,P.x); mxy=fmaxf(mxy,P.y); mxz=fmaxf(mxz,P.z);
        }
        atomicMin(&bbox[0], fenc(mnx)); atomicMin(&bbox[1], fenc(mny));
        atomicMin(&bbox[2], fenc(mnz));
        atomicMax(&bbox[3], fenc(mxx)); atomicMax(&bbox[4], fenc(mxy));
        atomicMax(&bbox[5], fenc(mxz));
    }
    __syncthreads();
    float bx0 = fdec(bbox[0]), by0 = fdec(bbox[1]), bz0 = fdec(bbox[2]);
    float sxc = 7.9999f / fmaxf(fdec(bbox[3]) - bx0, 1e-20f);
    float syc = 7.9999f / fmaxf(fdec(bbox[4]) - by0, 1e-20f);
    float szc = 7.9999f / fmaxf(fdec(bbox[5]) - bz0, 1e-20f);

    /* ---- 512-bucket morton bucket sort -> perm[] ---- */
    scan[t] = 0;
    __syncthreads();
    for (int c = t; c < Nv; c += TFPS){
        float4 P = ps[c];
        int ix = min(7, max(0, (int)((P.x-bx0)*sxc)));
        int iy = min(7, max(0, (int)((P.y-by0)*syc)));
        int iz = min(7, max(0, (int)((P.z-bz0)*szc)));
        atomicAdd(&scan[mor3(ix,iy,iz)], 1);
    }
    __syncthreads();
    int hcnt = scan[t];
    __syncthreads();
    for (int off = 1; off < TFPS; off <<= 1){
        int v = scan[t];
        int a = (t >= off) ? scan[t - off] : 0;
        __syncthreads();
        scan[t] = v + a;
        __syncthreads();
    }
    int hstart = scan[t] - hcnt;
    __syncthreads();
    scan[t] = hstart;
    __syncthreads();
    for (int c = t; c < Nv; c += TFPS){
        float4 P = ps[c];
        int ix = min(7, max(0, (int)((P.x-bx0)*sxc)));
        int iy = min(7, max(0, (int)((P.y-by0)*syc)));
        int iz = min(7, max(0, (int)((P.z-bz0)*szc)));
        int dst = atomicAdd(&scan[mor3(ix,iy,iz)], 1);
        perm[dst] = c;
    }
    if (t == 0){ bciA[0] = 0x7fffffff; bciA[1] = 0x7fffffff; }
    __syncthreads();

    /* ---- per-thread registers: 22 contiguous sorted points ---- */
    ull Xp[PMAX/2], Yp[PMAX/2], Zp[PMAX/2];
    unsigned Du[PMAX];
    float csx = 0.f, csy = 0.f, csz = 0.f;
    int   nreal = 0;
    {
        int p0 = perm[0];
        float fx[2], fy[2], fz[2];
        #pragma unroll
        for (int j = 0; j < PMAX/2; j++){
            #pragma unroll
            for (int h = 0; h < 2; h++){
                int sp = t*PMAX + 2*j + h;
                bool real = (sp < Nv);
                int src = real ? perm[sp] : p0;   /* pads mirror slot perm[0] */
                float4 P = ps[src];
                fx[h] = P.x; fy[h] = P.y; fz[h] = P.z;
                Du[2*j+h] = real ? __float_as_uint(1e10f) : 0u;
                if (real){ csx += fx[h]; csy += fy[h]; csz += fz[h]; nreal++; }
            }
            Xp[j] = pk2(fx[0], fx[1]);
            Yp[j] = pk2(fy[0], fy[1]);
            Zp[j] = pk2(fz[0], fz[1]);
        }
    }
    /* ---- warp ball: center + covering radius ---- */
    {
        #pragma unroll
        for (int off = 16; off > 0; off >>= 1){
            csx += __shfl_xor_sync(0xffffffffu, csx, off);
            csy += __shfl_xor_sync(0xffffffffu, csy, off);
            csz += __shfl_xor_sync(0xffffffffu, csz, off);
        }
        int cw = __reduce_add_sync(0xffffffffu, nreal);
        float invc = (cw > 0) ? (1.0f / (float)cw) : 0.f;
        float cx = csx*invc, cy = csy*invc, cz = csz*invc;
        float r2 = 0.f;
        #pragma unroll
        for (int j = 0; j < PMAX/2; j++){
            float a0,a1,b0,b1,c0,c1;
            upk2(Xp[j], a0, a1); upk2(Yp[j], b0, b1); upk2(Zp[j], c0, c1);
            float d0 = (a0-cx)*(a0-cx) + (b0-cy)*(b0-cy) + (c0-cz)*(c0-cz);
            float d1 = (a1-cx)*(a1-cx) + (b1-cy)*(b1-cy) + (c1-cz)*(c1-cz);
            r2 = fmaxf(r2, fmaxf(d0, d1));
        }
        unsigned r2w = __reduce_max_sync(0xffffffffu, __float_as_uint(r2));
        float rad = sqrtf(__uint_as_float(r2w)) * 1.0001f + 1e-5f;
        if (lane == 0) ball[w] = make_float4(cx, cy, cz, rad);
        __syncwarp();
    }
    unsigned lmax  = (nreal > 0) ? __float_as_uint(1e10f) : 0u;
    unsigned wmaxC = __reduce_max_sync(0xffffffffu, lmax);

    if (t == 0) g_fps[b*MPTS] = g_oi[b*NPTS];
    float4 P0v = ps[0];
    float px = P0v.x, py = P0v.y, pz = P0v.z;
    int par = 0;

    for (int m = 1; m < MPTS; m++){
        /* ---- warp-uniform conservative ball-prune test ---- */
        float4 B = ball[w];
        float dcx = B.x - px, dcy = B.y - py, dcz = B.z - pz;
        float dc2 = dcx*dcx + dcy*dcy + dcz*dcz;
        float lb  = sqrtf(dc2) - B.w;
        bool upd = !(lb > 0.f && lb*lb*0.999f >= __uint_as_float(wmaxC));

        if (upd){
            /* ---- region A: distance updates + local max tree ---- */
            ull nx = pk2(-px, -px), ny = pk2(-py, -py), nz = pk2(-pz, -pz);
            unsigned v[PMAX/2];
            #pragma unroll
            for (int p = 0; p < PMAX/2; p++){
                ull dx = add2(Xp[p], nx);               /* x - px */
                ull dy = add2(Yp[p], ny);
                ull dz = add2(Zp[p], nz);
                ull s  = add2(add2(mul2(dx,dx), mul2(dy,dy)), mul2(dz,dz));
                float d0, d1; upk2(s, d0, d1);
                unsigned n0 = min(Du[2*p],   __float_as_uint(d0));
                unsigned n1 = min(Du[2*p+1], __float_as_uint(d1));
                Du[2*p] = n0; Du[2*p+1] = n1;
                v[p] = max(n0, n1);
            }
            unsigned m0 = max(v[0], v[1]);
            unsigned m1 = max(v[2], v[3]);
            unsigned m2 = max(v[4], v[5]);
            unsigned m3 = max(v[6], v[7]);
            unsigned m4 = max(v[8], v[9]);
            unsigned q0 = max(m0, m1);
            unsigned q1 = max(m2, m3);
            unsigned q2 = max(m4, v[10]);
            lmax  = max(max(q0, q1), q2);
            wmaxC = __reduce_max_sync(0xffffffffu, lmax);
            if (lane == 0) redW[w] = wmaxC;   /* persists across pruned rounds */
        }
        __syncthreads();  /* bar1 */

        unsigned rv = (lane < 16) ? redW[lane] : 0u;
        unsigned bmax = __reduce_max_sync(0xffffffffu, rv);
        if (lmax == bmax){
            int c = 0x7fffffff;
            #pragma unroll
            for (int i = 0; i < PMAX; i++){
                if (Du[i] == bmax){
                    int sp = t*PMAX + i;
                    if (sp < Nv) c = min(c, perm[sp]);
                }
            }
            atomicMin(&bciA[par], c);
        }
        if (t == 0) bciA[par ^ 1] = 0x7fffffff;
        __syncthreads();  /* bar2 */

        int wc = bciA[par];          /* compacted slot: tie-break == reference */
        if (t == 0) g_fps[b*MPTS + m] = g_oi[b*NPTS + wc];
        float4 P = ps[wc];
        px = P.x; py = P.y; pz = P.z;
        par ^= 1;
    }
}

/* ---------- gather xyz + features by FPS indices ---------- */
__global__ void gather_kernel(const float* __restrict__ xyz, const float* __restrict__ feat,
                              float* __restrict__ oxyz, float* __restrict__ ofeat){
    int m = blockIdx.x, b = blockIdx.y;
    int j = g_fps[b*MPTS + m];
    int c = threadIdx.x;
    ofeat[((size_t)(b*MPTS + m))*CDIM + c] = feat[((size_t)b*NPTS + j)*CDIM + c];
    if (c < 3)
        oxyz[((size_t)(b*MPTS + m))*3 + c] = xyz[((size_t)b*NPTS + j)*3 + c];
}

/* ---------- stage 2: 2-NN affordance (d2 = sn + sq - 2*dot, as written) ---------- */
__global__ void nn_kernel(const float* __restrict__ dense, const float* __restrict__ sparse,
                          const float* __restrict__ scores, float* __restrict__ aff){
    __shared__ float sx[NS], sy[NS], sz[NS], sq[NS], sc[NS];
    __shared__ unsigned char sv[NS];
    int b = blockIdx.y;
    for (int i = threadIdx.x; i < NS; i += blockDim.x){
        float x = sparse[((size_t)b*NS + i)*3+0];
        float y = sparse[((size_t)b*NS + i)*3+1];
        float z = sparse[((size_t)b*NS + i)*3+2];
        sx[i]=x; sy[i]=y; sz[i]=z;
        sq[i] = __fadd_rn(__fadd_rn(__fmul_rn(x,x), __fmul_rn(y,y)), __fmul_rn(z,z));
        sv[i] = (x != 0.f || y != 0.f || z != 0.f) ? 1 : 0;
        sc[i] = scores[b*NS + i];
    }
    __syncthreads();
    int j = blockIdx.x * blockDim.x + threadIdx.x;
    float x = dense[((size_t)b*ND + j)*3+0];
    float y = dense[((size_t)b*ND + j)*3+1];
    float z = dense[((size_t)b*ND + j)*3+2];
    float sn = __fadd_rn(__fadd_rn(__fmul_rn(x,x), __fmul_rn(y,y)), __fmul_rn(z,z));
    float d1 = 3.3e38f, d2 = 3.3e38f; int i1 = 0, i2 = 0;
    for (int i = 0; i < NS; i++){
        float dot = __fadd_rn(__fadd_rn(__fmul_rn(x,sx[i]), __fmul_rn(y,sy[i])),
                              __fmul_rn(z,sz[i]));
        float dd  = sv[i] ? __fadd_rn(__fadd_rn(sn, sq[i]), __fmul_rn(-2.0f, dot)) : 1e10f;
        if (dd < d1){ d2 = d1; i2 = i1; d1 = dd; i1 = i; }
        else if (dd < d2){ d2 = dd; i2 = i; }
    }
    aff[b*ND + j] = __fmul_rn(__fadd_rn(sc[i1], sc[i2]), 0.5f);
}

/* ---------- stage 3a: best view per approach dir (argmax dot, tie->first) ---------- */
__global__ void vmax_kernel(const float* __restrict__ appr){
    int gtid = blockIdx.x * blockDim.x + threadIdx.x;
    int wid  = gtid >> 5;
    int lane = gtid & 31;
    if (wid >= B_BATCH*NS*3) return;
    const float* a = appr + (size_t)wid * 3;
    float ax = a[0], ay = a[1], az = a[2];
    float bm = -3.3e38f; int bv = 0x7fffffff;
    for (int v = lane; v < NVIEW; v += 32){
        float d = __fadd_rn(__fadd_rn(__fmul_rn(ax, g_views[v*3+0]),
                                      __fmul_rn(ay, g_views[v*3+1])),
                            __fmul_rn(az, g_views[v*3+2]));
        if (d > bm){ bm = d; bv = v; }
    }
    #pragma unroll
    for (int off = 16; off > 0; off >>= 1){
        float od = __shfl_down_sync(0xffffffffu, bm, off);
        int   ov = __shfl_down_sync(0xffffffffu, bv, off);
        if (od > bm || (od == bm && ov < bv)){ bm = od; bv = ov; }
    }
    if (lane == 0) g_vind[wid] = bv;
}

/* ---------- stage 3b: scatter (one thread per (b,n); k ascending -> last wins) ---------- */
__global__ void scatter_kernel(const float* __restrict__ sparse,
                               const float* __restrict__ nvs,
                               const float* __restrict__ ngs,
                               float* __restrict__ vs_out,
                               float* __restrict__ gs_out){
    int idx = blockIdx.x * blockDim.x + threadIdx.x;   /* b*NS + n */
    if (idx >= B_BATCH*NS) return;
    const float* sp = sparse + (size_t)idx * 3;
    float vm = (sp[0] != 0.f || sp[1] != 0.f || sp[2] != 0.f) ? 1.f : 0.f;
    for (int k = 0; k < 3; k++){
        int v = g_vind[idx*3 + k];
        vs_out[(size_t)idx*NVIEW + v] = __fmul_rn(nvs[idx*3 + k], vm);
        const float* src = ngs + ((size_t)(idx*3 + k)) * 84;
        float* dst = gs_out + ((size_t)idx*NVIEW + v) * 84;
        for (int j = 0; j < 84; j++) dst[j] = __fmul_rn(src[j], vm);
    }
}

extern "C" void kernel_launch(void* const* d_in, const int* in_sizes, int n_in,
                              void* d_out, int out_size){
    const float* seed_xyz   = (const float*)d_in[0];
    const float* seed_feat  = (const float*)d_in[1];
    const float* graspness  = (const float*)d_in[2];
    const float* dense      = (const float*)d_in[3];
    const float* sparse     = (const float*)d_in[4];
    const float* nscores    = (const float*)d_in[5];
    const float* appr       = (const float*)d_in[6];
    const float* nviewsc    = (const float*)d_in[7];
    const float* ngraspsc   = (const float*)d_in[8];
    float* out = (float*)d_out;

    static cudaStream_t s2;
    static cudaEvent_t  e1, e2;
    static int init_done = 0;
    if (!init_done){
        cudaStreamCreateWithFlags(&s2, cudaStreamNonBlocking);
        cudaEventCreateWithFlags(&e1, cudaEventDisableTiming);
        cudaEventCreateWithFlags(&e2, cudaEventDisableTiming);
        cudaFuncSetAttribute(fps_kernel, cudaFuncAttributeMaxDynamicSharedMemorySize,
                             SM_TOTAL);
        init_done = 1;
    }

    /* fork side stream (graph-capturable fork/join pattern) */
    cudaEventRecord(e1, 0);
    cudaStreamWaitEvent(s2, e1, 0);

    /* side stream: everything independent of FPS (overlaps the long fps kernel) */
    {
        size_t n4 = (size_t)(B_BATCH*NS*NVIEW + B_BATCH*NS*NVIEW*84) / 4;
        zero_kernel<<<2048, 256, 0, s2>>>((float4*)(out + O_VIEW), n4);
    }
    views_kernel<<<1, 256, 0, s2>>>();
    nn_kernel<<<dim3(ND/256, B_BATCH), 256, 0, s2>>>(dense, sparse, nscores, out + O_AFF);

    /* main stream: fps (1 block per batch) */
    fps_kernel<<<B_BATCH, TFPS, SM_TOTAL>>>(seed_xyz, graspness);

    vmax_kernel<<<(B_BATCH*NS*3*32 + 255)/256, 256, 0, s2>>>(appr);
    scatter_kernel<<<(B_BATCH*NS + 255)/256, 256, 0, s2>>>(sparse, nviewsc, ngraspsc,
                                                           out + O_VIEW, out + O_GRASP);
    cudaEventRecord(e2, s2);

    gather_kernel<<<dim3(MPTS, B_BATCH), CDIM>>>(seed_xyz, seed_feat,
                                                 out + O_XYZ, out + O_FEAT);
    /* join */
    cudaStreamWaitEvent(0, e2, 0);
    (void)in_sizes; (void)n_in; (void)out_size;
}

// round 9
// speedup vs baseline: 1.2677x; 1.2677x over previous
#include <cuda_runtime.h>
#include <math.h>
#include <stdint.h>

#define B_BATCH 2
#define NPTS    20480
#define MPTS    2048
#define CDIM    256
#define ND      16384
#define NS      512
#define NVIEW   800
#define GTH     0.001f

#define TFPS    256
#define PMAX    44                /* points per thread (fast path) */
#define NPAIR   (PMAX/2)          /* 22 f32x2 pairs                */
#define NVMAX   (TFPS*PMAX)       /* 11264 compacted-point capacity */

/* output offsets (floats), concatenated in reference return order */
#define O_XYZ   0
#define O_FEAT  (B_BATCH*MPTS*3)                    /* 12288    */
#define O_AFF   (O_FEAT + B_BATCH*MPTS*CDIM)        /* 1060864  */
#define O_VIEW  (O_AFF + B_BATCH*ND)                /* 1093632  */
#define O_GRASP (O_VIEW + B_BATCH*NS*NVIEW)         /* 1912832  */

/* fps smem layout (bytes) */
#define SM_PS    0                          /* float4 ps[NVMAX] (180224B) */
#define SM_WIN   (SM_PS + NVMAX*16)         /* int win[MPTS]    (8192B)   */
#define SM_SCAN  (SM_WIN + MPTS*4)          /* int scan[TFPS]   (1024B)   */
#define SM_AUX   (SM_SCAN + TFPS*4)         /* redW[8] + bciA[2] + pad    */
#define SM_TOTAL (SM_AUX + 16*4)

typedef unsigned long long ull;

__device__ float g_views[NVIEW*3];
__device__ int   g_oi[B_BATCH*NPTS];     /* compacted -> original index */
__device__ float g_cc[B_BATCH*NPTS*3];   /* fallback compacted coords   */
__device__ int   g_fps[B_BATCH*MPTS];    /* FPS-selected original idx   */
__device__ int   g_vind[B_BATCH*NS*3];   /* per-approach best view      */

/* ---------- packed f32x2 helpers (per-lane identical to scalar .rn) ---------- */
__device__ __forceinline__ ull pk2(float a, float b){
    ull r; asm("mov.b64 %0, {%1,%2};" : "=l"(r) : "f"(a), "f"(b)); return r;
}
__device__ __forceinline__ void upk2(ull v, float &a, float &b){
    asm("mov.b64 {%0,%1}, %2;" : "=f"(a), "=f"(b) : "l"(v));
}
__device__ __forceinline__ ull add2(ull a, ull b){
    ull r; asm("add.rn.f32x2 %0, %1, %2;" : "=l"(r) : "l"(a), "l"(b)); return r;
}
__device__ __forceinline__ ull mul2(ull a, ull b){
    ull r; asm("mul.rn.f32x2 %0, %1, %2;" : "=l"(r) : "l"(a), "l"(b)); return r;
}

/* ---------- view templates: fp64 Fibonacci sphere, matches numpy ---------- */
__global__ void views_kernel(){
    const double phi = (sqrt(5.0) - 1.0) * 0.5;
    for (int i = threadIdx.x; i < NVIEW; i += blockDim.x){
        double zi = (2.0 * (double)i + 1.0) / (double)NVIEW - 1.0;
        double r2 = 1.0 - zi * zi; if (r2 < 0.0) r2 = 0.0;
        double r  = sqrt(r2);
        double ang = 2.0 * 3.141592653589793 * (double)i * phi;
        g_views[i*3+0] = (float)(r * cos(ang));
        g_views[i*3+1] = (float)(r * sin(ang));
        g_views[i*3+2] = (float)zi;
    }
}

/* ---------- zero-fill the scatter outputs (128-bit stores) ---------- */
__global__ void zero_kernel(float4* __restrict__ p, size_t n4){
    size_t stride = (size_t)gridDim.x * blockDim.x;
    for (size_t i = (size_t)blockIdx.x * blockDim.x + threadIdx.x; i < n4; i += stride)
        p[i] = make_float4(0.f, 0.f, 0.f, 0.f);
}

/* ---------- generic block argmax for 8 warps (fallback path only) ---------- */
__device__ __forceinline__ int block_argmax8(float bestd, int bestc,
                                             float* redD, int* redC, int* bci, int t){
    #pragma unroll
    for (int off = 16; off > 0; off >>= 1){
        float od = __shfl_down_sync(0xffffffffu, bestd, off);
        int   oc = __shfl_down_sync(0xffffffffu, bestc, off);
        if (od > bestd || (od == bestd && oc < bestc)){ bestd = od; bestc = oc; }
    }
    if ((t & 31) == 0){ redD[t>>5] = bestd; redC[t>>5] = bestc; }
    __syncthreads();
    if (t < 32){
        float bd  = (t < 8) ? redD[t] : -3.3e38f;
        int   bcv = (t < 8) ? redC[t] : 0x7fffffff;
        #pragma unroll
        for (int off = 4; off > 0; off >>= 1){
            float od = __shfl_down_sync(0xffffffffu, bd, off);
            int   oc = __shfl_down_sync(0xffffffffu, bcv, off);
            if (od > bd || (od == bd && oc < bcv)){ bd = od; bcv = oc; }
        }
        if (t == 0) *bci = bcv;
    }
    __syncthreads();
    return *bci;
}

/* ---------- masked FPS, one block per batch ---------- */
__global__ void __launch_bounds__(TFPS, 1)
fps_kernel(const float* __restrict__ xyz, const float* __restrict__ gsc){
    extern __shared__ unsigned char fsm[];
    const int b = blockIdx.x;
    const int t = threadIdx.x;
    const int lane = t & 31;
    const int w = t >> 5;
    const float* X = xyz + (size_t)b * NPTS * 3;
    const float* G = gsc + (size_t)b * NPTS;

    float4*   ps   = (float4*)(fsm + SM_PS);
    int*      win  = (int*)(fsm + SM_WIN);
    int*      scan = (int*)(fsm + SM_SCAN);
    unsigned* redW = (unsigned*)(fsm + SM_AUX);    /* [8]  */
    int*      bciA = (int*)(fsm + SM_AUX) + 8;     /* [2]  */

    /* ---- order-preserving compaction of graspable points ---- */
    const int CH = NPTS / TFPS;  /* 80 */
    int base = t * CH;
    int cnt = 0;
    for (int j = 0; j < CH; j++) cnt += (G[base + j] > GTH) ? 1 : 0;
    scan[t] = cnt;
    __syncthreads();
    for (int off = 1; off < TFPS; off <<= 1){
        int v = scan[t];
        int a = (t >= off) ? scan[t - off] : 0;
        __syncthreads();
        scan[t] = v + a;
        __syncthreads();
    }
    int Nv  = scan[TFPS - 1];
    int pos = scan[t] - cnt;
    bool fast = (Nv <= NVMAX);
    for (int j = 0; j < CH; j++){
        int idx = base + j;
        if (G[idx] > GTH){
            float x = X[idx*3+0], y = X[idx*3+1], z = X[idx*3+2];
            if (fast){
                ps[pos] = make_float4(x, y, z, 0.f);
            } else {
                size_t gp = ((size_t)b * NPTS + pos) * 3;
                g_cc[gp] = x; g_cc[gp+1] = y; g_cc[gp+2] = z;
            }
            g_oi[b*NPTS + pos] = idx;
            pos++;
        }
    }
    if (t == 0){ bciA[0] = 0x7fffffff; bciA[1] = 0x7fffffff; win[0] = 0; }
    __syncthreads();

    if (Nv <= 0){
        for (int m = t; m < MPTS; m += TFPS) g_fps[b*MPTS + m] = 0;
        return;
    }

    if (!fast){
        /* fallback (statistically unreachable): dists in smem, coords global */
        float* dst  = (float*)ps;          /* ps region: room for NPTS floats */
        float* redD = (float*)scan;
        int*   redC = (int*)(redD + 8);
        int*   bci  = redC + 8;
        for (int c = t; c < Nv; c += TFPS) dst[c] = 1e10f;
        if (t == 0) g_fps[b*MPTS] = g_oi[b*NPTS];
        __syncthreads();
        float px = g_cc[(size_t)b*NPTS*3+0];
        float py = g_cc[(size_t)b*NPTS*3+1];
        float pz = g_cc[(size_t)b*NPTS*3+2];
        for (int m = 1; m < MPTS; m++){
            float bestd = -1.0f; int bestc = 0x7fffffff;
            for (int c = t; c < Nv; c += TFPS){
                const float* P = &g_cc[((size_t)b*NPTS + c)*3];
                float dx = __fadd_rn(P[0], -px);
                float dy = __fadd_rn(P[1], -py);
                float dz = __fadd_rn(P[2], -pz);
                float d  = __fadd_rn(__fadd_rn(__fmul_rn(dx,dx), __fmul_rn(dy,dy)),
                                     __fmul_rn(dz,dz));
                float nd = fminf(dst[c], d);
                dst[c] = nd;
                if (nd > bestd){ bestd = nd; bestc = c; }
            }
            int wc = block_argmax8(bestd, bestc, redD, redC, bci, t);
            if (t == 0) g_fps[b*MPTS + m] = g_oi[b*NPTS + wc];
            const float* P = &g_cc[((size_t)b*NPTS + wc)*3];
            px = P[0]; py = P[1]; pz = P[2];
            __syncthreads();
        }
        return;
    }

    /* ================= fast path ================= */
    /* register-resident points; pads mirror slot 0 (distance mirrors slot 0;
       at the argmax, slot 0 itself also matches and wins the atomicMin)     */
    ull Xp[NPAIR], Yp[NPAIR], Zp[NPAIR];
    unsigned Du[PMAX];
    #pragma unroll
    for (int p = 0; p < NPAIR; p++){
        int c0 = t + (2*p) * TFPS;
        int c1 = c0 + TFPS;
        float4 P0 = ps[(c0 < Nv) ? c0 : 0];
        float4 P1 = ps[(c1 < Nv) ? c1 : 0];
        Xp[p] = pk2(P0.x, P1.x);
        Yp[p] = pk2(P0.y, P1.y);
        Zp[p] = pk2(P0.z, P1.z);
        Du[2*p] = __float_as_uint(1e10f); Du[2*p+1] = __float_as_uint(1e10f);
    }
    float4 P0v = ps[0];
    float px = P0v.x, py = P0v.y, pz = P0v.z;
    int par = 0;

    for (int m = 1; m < MPTS; m++){
        /* ---- region A: distance updates + local max tree ---- */
        ull nx = pk2(-px, -px), ny = pk2(-py, -py), nz = pk2(-pz, -pz);
        unsigned v[NPAIR];
        #pragma unroll
        for (int p = 0; p < NPAIR; p++){
            ull dx = add2(Xp[p], nx);               /* x - px */
            ull dy = add2(Yp[p], ny);
            ull dz = add2(Zp[p], nz);
            ull s  = add2(add2(mul2(dx,dx), mul2(dy,dy)), mul2(dz,dz));
            float d0, d1; upk2(s, d0, d1);
            unsigned n0 = min(Du[2*p],   __float_as_uint(d0));
            unsigned n1 = min(Du[2*p+1], __float_as_uint(d1));
            Du[2*p] = n0; Du[2*p+1] = n1;
            v[p] = max(n0, n1);
        }
        /* 22 -> 1 max tree, depth 5, compile-time indices */
        #pragma unroll
        for (int i = 0; i < 11; i++) v[i] = max(v[i], v[i+11]);
        #pragma unroll
        for (int i = 0; i < 5; i++)  v[i] = max(v[i], v[i+6]);
        #pragma unroll
        for (int i = 0; i < 3; i++)  v[i] = max(v[i], v[i+3]);
        unsigned localmax = max(max(v[0], v[1]), v[2]);

        unsigned wmax = __reduce_max_sync(0xffffffffu, localmax);
        if (lane == 0) redW[w] = wmax;
        __syncthreads();  /* bar1 */

        /* ---- block max, winner rescan, reset other slot ---- */
        unsigned rv = (lane < 8) ? redW[lane] : 0u;
        unsigned bmax = __reduce_max_sync(0xffffffffu, rv);
        if (localmax == bmax){
            int c = 0x7fffffff;
            #pragma unroll
            for (int i = 0; i < PMAX; i++)
                if (Du[i] == bmax) c = min(c, t + i*TFPS);
            atomicMin(&bciA[par], c);
        }
        if (t == 0) bciA[par ^ 1] = 0x7fffffff;
        __syncthreads();  /* bar2 */

        int wc = bciA[par];
        if (t == 0) win[m] = wc;          /* STS only: no global on the loop path */
        float4 P = ps[wc];
        px = P.x; py = P.y; pz = P.z;
        par ^= 1;
    }

    /* ---- deferred slot -> original-index translation ---- */
    __syncthreads();
    for (int m = t; m < MPTS; m += TFPS)
        g_fps[b*MPTS + m] = g_oi[b*NPTS + win[m]];
}

/* ---------- gather xyz + features by FPS indices ---------- */
__global__ void gather_kernel(const float* __restrict__ xyz, const float* __restrict__ feat,
                              float* __restrict__ oxyz, float* __restrict__ ofeat){
    int m = blockIdx.x, b = blockIdx.y;
    int j = g_fps[b*MPTS + m];
    int c = threadIdx.x;
    ofeat[((size_t)(b*MPTS + m))*CDIM + c] = feat[((size_t)b*NPTS + j)*CDIM + c];
    if (c < 3)
        oxyz[((size_t)(b*MPTS + m))*3 + c] = xyz[((size_t)b*NPTS + j)*3 + c];
}

/* ---------- stage 2: 2-NN affordance (d2 = sn + sq - 2*dot, as written) ---------- */
__global__ void nn_kernel(const float* __restrict__ dense, const float* __restrict__ sparse,
                          const float* __restrict__ scores, float* __restrict__ aff){
    __shared__ float sx[NS], sy[NS], sz[NS], sq[NS], sc[NS];
    __shared__ unsigned char sv[NS];
    int b = blockIdx.y;
    for (int i = threadIdx.x; i < NS; i += blockDim.x){
        float x = sparse[((size_t)b*NS + i)*3+0];
        float y = sparse[((size_t)b*NS + i)*3+1];
        float z = sparse[((size_t)b*NS + i)*3+2];
        sx[i]=x; sy[i]=y; sz[i]=z;
        sq[i] = __fadd_rn(__fadd_rn(__fmul_rn(x,x), __fmul_rn(y,y)), __fmul_rn(z,z));
        sv[i] = (x != 0.f || y != 0.f || z != 0.f) ? 1 : 0;
        sc[i] = scores[b*NS + i];
    }
    __syncthreads();
    int j = blockIdx.x * blockDim.x + threadIdx.x;
    float x = dense[((size_t)b*ND + j)*3+0];
    float y = dense[((size_t)b*ND + j)*3+1];
    float z = dense[((size_t)b*ND + j)*3+2];
    float sn = __fadd_rn(__fadd_rn(__fmul_rn(x,x), __fmul_rn(y,y)), __fmul_rn(z,z));
    float d1 = 3.3e38f, d2 = 3.3e38f; int i1 = 0, i2 = 0;
    for (int i = 0; i < NS; i++){
        float dot = __fadd_rn(__fadd_rn(__fmul_rn(x,sx[i]), __fmul_rn(y,sy[i])),
                              __fmul_rn(z,sz[i]));
        float dd  = sv[i] ? __fadd_rn(__fadd_rn(sn, sq[i]), __fmul_rn(-2.0f, dot)) : 1e10f;
        if (dd < d1){ d2 = d1; i2 = i1; d1 = dd; i1 = i; }
        else if (dd < d2){ d2 = dd; i2 = i; }
    }
    aff[b*ND + j] = __fmul_rn(__fadd_rn(sc[i1], sc[i2]), 0.5f);
}

/* ---------- stage 3a: best view per approach dir (argmax dot, tie->first) ---------- */
__global__ void vmax_kernel(const float* __restrict__ appr){
    int gtid = blockIdx.x * blockDim.x + threadIdx.x;
    int wid  = gtid >> 5;
    int lane = gtid & 31;
    if (wid >= B_BATCH*NS*3) return;
    const float* a = appr + (size_t)wid * 3;
    float ax = a[0], ay = a[1], az = a[2];
    float bm = -3.3e38f; int bv = 0x7fffffff;
    for (int v = lane; v < NVIEW; v += 32){
        float d = __fadd_rn(__fadd_rn(__fmul_rn(ax, g_views[v*3+0]),
                                      __fmul_rn(ay, g_views[v*3+1])),
                            __fmul_rn(az, g_views[v*3+2]));
        if (d > bm){ bm = d; bv = v; }
    }
    #pragma unroll
    for (int off = 16; off > 0; off >>= 1){
        float od = __shfl_down_sync(0xffffffffu, bm, off);
        int   ov = __shfl_down_sync(0xffffffffu, bv, off);
        if (od > bm || (od == bm && ov < bv)){ bm = od; bv = ov; }
    }
    if (lane == 0) g_vind[wid] = bv;
}

/* ---------- stage 3b: scatter (one thread per (b,n); k ascending -> last wins) ---------- */
__global__ void scatter_kernel(const float* __restrict__ sparse,
                               const float* __restrict__ nvs,
                               const float* __restrict__ ngs,
                               float* __restrict__ vs_out,
                               float* __restrict__ gs_out){
    int idx = blockIdx.x * blockDim.x + threadIdx.x;   /* b*NS + n */
    if (idx >= B_BATCH*NS) return;
    const float* sp = sparse + (size_t)idx * 3;
    float vm = (sp[0] != 0.f || sp[1] != 0.f || sp[2] != 0.f) ? 1.f : 0.f;
    for (int k = 0; k < 3; k++){
        int v = g_vind[idx*3 + k];
        vs_out[(size_t)idx*NVIEW + v] = __fmul_rn(nvs[idx*3 + k], vm);
        const float* src = ngs + ((size_t)(idx*3 + k)) * 84;
        float* dst = gs_out + ((size_t)idx*NVIEW + v) * 84;
        for (int j = 0; j < 84; j++) dst[j] = __fmul_rn(src[j], vm);
    }
}

extern "C" void kernel_launch(void* const* d_in, const int* in_sizes, int n_in,
                              void* d_out, int out_size){
    const float* seed_xyz   = (const float*)d_in[0];
    const float* seed_feat  = (const float*)d_in[1];
    const float* graspness  = (const float*)d_in[2];
    const float* dense      = (const float*)d_in[3];
    const float* sparse     = (const float*)d_in[4];
    const float* nscores    = (const float*)d_in[5];
    const float* appr       = (const float*)d_in[6];
    const float* nviewsc    = (const float*)d_in[7];
    const float* ngraspsc   = (const float*)d_in[8];
    float* out = (float*)d_out;

    static cudaStream_t s2;
    static cudaEvent_t  e1, e2;
    static int init_done = 0;
    if (!init_done){
        cudaStreamCreateWithFlags(&s2, cudaStreamNonBlocking);
        cudaEventCreateWithFlags(&e1, cudaEventDisableTiming);
        cudaEventCreateWithFlags(&e2, cudaEventDisableTiming);
        cudaFuncSetAttribute(fps_kernel, cudaFuncAttributeMaxDynamicSharedMemorySize,
                             SM_TOTAL);
        init_done = 1;
    }

    /* fork side stream (graph-capturable fork/join pattern) */
    cudaEventRecord(e1, 0);
    cudaStreamWaitEvent(s2, e1, 0);

    /* side stream: everything independent of FPS (overlaps the long fps kernel) */
    {
        size_t n4 = (size_t)(B_BATCH*NS*NVIEW + B_BATCH*NS*NVIEW*84) / 4;
        zero_kernel<<<2048, 256, 0, s2>>>((float4*)(out + O_VIEW), n4);
    }
    views_kernel<<<1, 256, 0, s2>>>();
    nn_kernel<<<dim3(ND/256, B_BATCH), 256, 0, s2>>>(dense, sparse, nscores, out + O_AFF);

    /* main stream: fps (1 block per batch) */
    fps_kernel<<<B_BATCH, TFPS, SM_TOTAL>>>(seed_xyz, graspness);

    vmax_kernel<<<(B_BATCH*NS*3*32 + 255)/256, 256, 0, s2>>>(appr);
    scatter_kernel<<<(B_BATCH*NS + 255)/256, 256, 0, s2>>>(sparse, nviewsc, ngraspsc,
                                                           out + O_VIEW, out + O_GRASP);
    cudaEventRecord(e2, s2);

    gather_kernel<<<dim3(MPTS, B_BATCH), CDIM>>>(seed_xyz, seed_feat,
                                                 out + O_XYZ, out + O_FEAT);
    /* join */
    cudaStreamWaitEvent(0, e2, 0);
    (void)in_sizes; (void)n_in; (void)out_size;
}